// round 17
// baseline (speedup 1.0000x reference)
#include <cuda_runtime.h>

// Problem constants: B=8, L=1024, D=512, T=16
#define M_ROWS 8192          // B*L
#define K_DIM  512           // D
#define N_COLS 8192          // D*T
#define T_STEPS 16
#define PER_T_COUNT 4194304  // M_ROWS * D  (elements per BN channel)

typedef unsigned long long u64;

// ---------------- scratch (static device globals; no allocation) ----------
__device__ float g_xn[M_ROWS * K_DIM];               // 16 MB  layernormed input
__device__ float g_y[(size_t)M_ROWS * N_COLS];       // 256 MB GEMM output
__device__ float g_part[M_ROWS * 32];                // per-row BN partials
__device__ float g_bin[32];                          // reduced sums / sumsq
__device__ float g_stats[32];                        // mean[16], invstd[16]

// ---------------- packed f32x2 helpers (FFMA2 path, sm_103a) --------------
__device__ __forceinline__ void fma2(u64& c, u64 a, u64 b) {
    asm("fma.rn.f32x2 %0, %1, %2, %0;" : "+l"(c) : "l"(a), "l"(b));
}
__device__ __forceinline__ float2 unpack2(u64 v) {
    float2 f; asm("mov.b64 {%0, %1}, %2;" : "=f"(f.x), "=f"(f.y) : "l"(v)); return f;
}

// ---------------- 1. LayerNorm over D (EXACT R7) --------------------------
__global__ __launch_bounds__(128) void ln_kernel(const float* __restrict__ x,
                                                 const float* __restrict__ g,
                                                 const float* __restrict__ bb) {
    const int row = blockIdx.x;
    const int tid = threadIdx.x;
    const unsigned lane = tid & 31, wid = tid >> 5;
    __shared__ float r4[4];

    const float4* xr = (const float4*)(x + (size_t)row * K_DIM);
    float4 v = xr[tid];

    float s = (v.x + v.y) + (v.z + v.w);
    #pragma unroll
    for (int o = 16; o; o >>= 1) s += __shfl_xor_sync(0xffffffffu, s, o);
    if (!lane) r4[wid] = s;
    __syncthreads();
    float mean = (r4[0] + r4[1] + r4[2] + r4[3]) * (1.0f / 512.0f);
    __syncthreads();

    float dx = v.x - mean, dy = v.y - mean, dz = v.z - mean, dw = v.w - mean;
    float q = (dx * dx + dy * dy) + (dz * dz + dw * dw);
    #pragma unroll
    for (int o = 16; o; o >>= 1) q += __shfl_xor_sync(0xffffffffu, q, o);
    if (!lane) r4[wid] = q;
    __syncthreads();
    float var = (r4[0] + r4[1] + r4[2] + r4[3]) * (1.0f / 512.0f);
    float rstd = 1.0f / sqrtf(var + 1e-5f);

    const int c = tid * 4;
    float4 o4;
    o4.x = dx * rstd * g[c + 0] + bb[c + 0];
    o4.y = dy * rstd * g[c + 1] + bb[c + 1];
    o4.z = dz * rstd * g[c + 2] + bb[c + 2];
    o4.w = dw * rstd * g[c + 3] + bb[c + 3];
    ((float4*)(g_xn + (size_t)row * K_DIM))[tid] = o4;
}

// ---------------- 2. fp32 GEMM (FFMA2 order EXACT R7; k-chunk 32) ---------
// 128x128 tiles, 8x8/thread. Per-output FFMA2 sequence walks k=0..511 in
// order with identical operand pairing -> g_y bitwise identical to R7.
// Changes are scheduling-only: 32-deep k-chunks (half the syncs), dynamic
// smem double buffer, split-wave staging (A then B) to cap register peak.
#define A_STRIDE 260   // floats per k-row of dup'd A
#define B_STRIDE 132   // floats per k-row of B
#define A_BUF (32 * A_STRIDE)          // 8320 floats
#define B_BUF (32 * B_STRIDE)          // 4224 floats
#define GEMM_SMEM ((2 * A_BUF + 2 * B_BUF) * 4)   // 100352 bytes

__global__ __launch_bounds__(256, 2) void gemm_kernel(const float* __restrict__ Wm,
                                                      const float* __restrict__ bias) {
    extern __shared__ float dsm[];
    float* Asm = dsm;                 // 2 * A_BUF
    float* Bsm = dsm + 2 * A_BUF;     // 2 * B_BUF

    const int tid  = threadIdx.x;
    const int brow = blockIdx.y << 7;
    const int bcol = blockIdx.x << 7;
    const int tx = tid & 15;          // N sub-tile: cols {4tx..+3, 64+4tx..+3}
    const int ty = tid >> 4;          // M sub-tile
    const int lrow = tid >> 2;        // 0..63 (loader row; also +64)
    const int lk8  = (tid & 3) << 3;  // 0,8,16,24 (loader k base, 8 wide)

    u64 acc[8][4];
    #pragma unroll
    for (int i = 0; i < 8; i++)
        #pragma unroll
        for (int j = 0; j < 4; j++) acc[i][j] = 0ull;

    const float* Ag = g_xn + (size_t)(brow + lrow) * K_DIM + lk8;
    const float* Bg = Wm   + (size_t)(bcol + lrow) * K_DIM + lk8;

    // ---- staging helpers (A wave, then B wave) ----
    auto stsA = [&](float* dst, float4 a0, float4 a0b, float4 a1, float4 a1b) {
        float av0[8] = {a0.x, a0.y, a0.z, a0.w, a0b.x, a0b.y, a0b.z, a0b.w};
        float av1[8] = {a1.x, a1.y, a1.z, a1.w, a1b.x, a1b.y, a1b.z, a1b.w};
        #pragma unroll
        for (int j = 0; j < 8; j++) {
            const int kr = lk8 + j;
            float2 d0 = {av0[j], av0[j]};
            float2 d1 = {av1[j], av1[j]};
            *(float2*)&dst[kr * A_STRIDE + 2 * lrow]       = d0;
            *(float2*)&dst[kr * A_STRIDE + 2 * lrow + 128] = d1;
        }
    };
    auto stsB = [&](float* dst, float4 b0, float4 b0b, float4 b1, float4 b1b) {
        float bv0[8] = {b0.x, b0.y, b0.z, b0.w, b0b.x, b0b.y, b0b.z, b0b.w};
        float bv1[8] = {b1.x, b1.y, b1.z, b1.w, b1b.x, b1b.y, b1b.z, b1b.w};
        #pragma unroll
        for (int j = 0; j < 8; j++) {
            const int kr = lk8 + j;
            dst[kr * B_STRIDE + lrow]      = bv0[j];
            dst[kr * B_STRIDE + lrow + 64] = bv1[j];
        }
    };
    // compute 16 k-steps starting at k0 within buffer (EXACT R7 inner body)
    auto computeHalf = [&](const float* Ab, const float* Bb, int k0) {
        #pragma unroll
        for (int kl = 0; kl < 16; ++kl) {
            const int k = k0 + kl;
            ulonglong2 aA = *(const ulonglong2*)&Ab[k * A_STRIDE + 8 * ty];
            ulonglong2 aB = *(const ulonglong2*)&Ab[k * A_STRIDE + 8 * ty + 4];
            ulonglong2 aC = *(const ulonglong2*)&Ab[k * A_STRIDE + 8 * ty + 128];
            ulonglong2 aD = *(const ulonglong2*)&Ab[k * A_STRIDE + 8 * ty + 132];
            ulonglong2 b0 = *(const ulonglong2*)&Bb[k * B_STRIDE + 4 * tx];
            ulonglong2 b1 = *(const ulonglong2*)&Bb[k * B_STRIDE + 4 * tx + 64];
            u64 a_[8] = {aA.x, aA.y, aB.x, aB.y, aC.x, aC.y, aD.x, aD.y};
            u64 b_[4] = {b0.x, b0.y, b1.x, b1.y};
            #pragma unroll
            for (int i = 0; i < 8; i++) {
                fma2(acc[i][0], a_[i], b_[0]);
                fma2(acc[i][1], a_[i], b_[1]);
                fma2(acc[i][2], a_[i], b_[2]);
                fma2(acc[i][3], a_[i], b_[3]);
            }
        }
    };

    // ---- prologue: full tile 0 (A wave, then B wave) ----
    {
        float4 a0  = *(const float4*)(Ag);
        float4 a0b = *(const float4*)(Ag + 4);
        float4 a1  = *(const float4*)(Ag + (size_t)64 * K_DIM);
        float4 a1b = *(const float4*)(Ag + (size_t)64 * K_DIM + 4);
        stsA(Asm, a0, a0b, a1, a1b);
        float4 b0  = *(const float4*)(Bg);
        float4 b0b = *(const float4*)(Bg + 4);
        float4 b1  = *(const float4*)(Bg + (size_t)64 * K_DIM);
        float4 b1b = *(const float4*)(Bg + (size_t)64 * K_DIM + 4);
        stsB(Bsm, b0, b0b, b1, b1b);
    }
    __syncthreads();

    int buf = 0;
    for (int kk = 0; kk < K_DIM; kk += 32) {
        const bool has_next = (kk + 32) < K_DIM;
        const float* Ab = Asm + buf * A_BUF;
        const float* Bb = Bsm + buf * B_BUF;
        float* An = Asm + (buf ^ 1) * A_BUF;
        float* Bn = Bsm + (buf ^ 1) * B_BUF;

        // A-wave prefetch for next tile
        float4 na0, na0b, na1, na1b;
        if (has_next) {
            na0  = *(const float4*)(Ag + kk + 32);
            na0b = *(const float4*)(Ag + kk + 36);
            na1  = *(const float4*)(Ag + kk + 32 + (size_t)64 * K_DIM);
            na1b = *(const float4*)(Ag + kk + 36 + (size_t)64 * K_DIM);
        }

        computeHalf(Ab, Bb, 0);

        float4 nb0, nb0b, nb1, nb1b;
        if (has_next) {
            stsA(An, na0, na0b, na1, na1b);
            nb0  = *(const float4*)(Bg + kk + 32);
            nb0b = *(const float4*)(Bg + kk + 36);
            nb1  = *(const float4*)(Bg + kk + 32 + (size_t)64 * K_DIM);
            nb1b = *(const float4*)(Bg + kk + 36 + (size_t)64 * K_DIM);
        }

        computeHalf(Ab, Bb, 16);

        if (has_next) {
            stsB(Bn, nb0, nb0b, nb1, nb1b);
            __syncthreads();
            buf ^= 1;
        }
    }

    // ---- epilogue: + bias, write g_y (EXACT R7) ----
    float bv[8];
    #pragma unroll
    for (int j = 0; j < 4; j++) bv[j]     = bias[bcol + (tx << 2) + j];
    #pragma unroll
    for (int j = 0; j < 4; j++) bv[4 + j] = bias[bcol + 64 + (tx << 2) + j];

    #pragma unroll
    for (int i = 0; i < 8; i++) {
        const int row = brow + ((i < 4) ? ((ty << 2) + i) : (64 + (ty << 2) + i - 4));
        float* cp = g_y + (size_t)row * N_COLS + bcol + (tx << 2);
        float2 f0 = unpack2(acc[i][0]);
        float2 f1 = unpack2(acc[i][1]);
        float2 f2 = unpack2(acc[i][2]);
        float2 f3 = unpack2(acc[i][3]);
        float4 o0 = {f0.x + bv[0], f0.y + bv[1], f1.x + bv[2], f1.y + bv[3]};
        float4 o1 = {f2.x + bv[4], f2.y + bv[5], f3.x + bv[6], f3.y + bv[7]};
        *(float4*)cp = o0;
        *(float4*)(cp + 64) = o1;
    }
}

// ---------------- 3. BN stats (EXACT R7) ----------------------------------
__global__ __launch_bounds__(256) void stats_kernel() {
    const int row = blockIdx.x;
    const int tid = threadIdx.x;
    const float* yr = g_y + (size_t)row * N_COLS;
    float s = 0.f, q = 0.f;
    #pragma unroll 8
    for (int j = 0; j < 32; j++) {
        float v = yr[tid + (j << 8)];   // col % 16 == tid % 16 for all j
        s += v;
        q += v * v;
    }
    __shared__ float sh[512];
    sh[tid] = s;
    sh[256 + tid] = q;
    __syncthreads();
    if (tid < 32) {
        const int base = (tid < 16) ? tid : (256 + tid - 16);
        float a = 0.f;
        #pragma unroll
        for (int j = 0; j < 16; j++) a += sh[base + (j << 4)];
        g_part[row * 32 + tid] = a;
    }
}

__global__ __launch_bounds__(256) void reduce_kernel() {
    const int bin = blockIdx.x;
    const int tid = threadIdx.x;
    float s = 0.f;
    for (int r = tid; r < M_ROWS; r += 256) s += g_part[r * 32 + bin];
    __shared__ float sh[256];
    sh[tid] = s;
    __syncthreads();
    #pragma unroll
    for (int o = 128; o; o >>= 1) {
        if (tid < o) sh[tid] += sh[tid + o];
        __syncthreads();
    }
    if (!tid) g_bin[bin] = sh[0];
}

__global__ void finalize_kernel() {
    const int t = threadIdx.x;  // 16 threads
    float mean = g_bin[t] * (1.0f / (float)PER_T_COUNT);
    float ex2  = g_bin[16 + t] * (1.0f / (float)PER_T_COUNT);
    float var  = ex2 - mean * mean;
    g_stats[t] = mean;
    g_stats[16 + t] = 1.0f / sqrtf(var + 1e-5f);
}

// ---------------- 4. BN + LIF (4 neurons/thread; per-neuron math EXACT R7) -
__global__ __launch_bounds__(256) void lif_kernel(const float* __restrict__ bng,
                                                  const float* __restrict__ bnb,
                                                  const float* __restrict__ th,
                                                  float* __restrict__ out) {
    __shared__ float sm[16], si[16], sg[16], sb[16];
    const int tid = threadIdx.x;
    if (tid < 16) {
        sm[tid] = g_stats[tid];
        si[tid] = g_stats[16 + tid];
        sg[tid] = bng[tid];
        sb[tid] = bnb[tid];
    }
    __syncthreads();
    const float thr = __ldg(th);

    const unsigned gid = blockIdx.x * 256u + tid;  // 0 .. 1048575
    const unsigned m = gid >> 7;
    const unsigned d = (gid & 127u) << 2;          // neuron base (mult of 4)

    const float4* yp = (const float4*)(g_y + ((size_t)m << 13) + ((size_t)d << 4));
    float4 q[16];
    #pragma unroll
    for (int i = 0; i < 16; i++) q[i] = yp[i];     // 4 neurons x 16 t

    float v0 = 0.f, v1 = 0.f, v2 = 0.f, v3 = 0.f;
    const size_t ob = ((size_t)m << 9) + d;
    #pragma unroll
    for (int t = 0; t < T_STEPS; t++) {
        const int qi = t >> 2, qc = t & 3;
        float x0 = (qc == 0) ? q[qi].x : (qc == 1) ? q[qi].y : (qc == 2) ? q[qi].z : q[qi].w;
        float x1 = (qc == 0) ? q[4 + qi].x : (qc == 1) ? q[4 + qi].y : (qc == 2) ? q[4 + qi].z : q[4 + qi].w;
        float x2 = (qc == 0) ? q[8 + qi].x : (qc == 1) ? q[8 + qi].y : (qc == 2) ? q[8 + qi].z : q[8 + qi].w;
        float x3 = (qc == 0) ? q[12 + qi].x : (qc == 1) ? q[12 + qi].y : (qc == 2) ? q[12 + qi].z : q[12 + qi].w;

        float val0 = (x0 - sm[t]) * si[t]; val0 = val0 * sg[t] + sb[t];
        float val1 = (x1 - sm[t]) * si[t]; val1 = val1 * sg[t] + sb[t];
        float val2 = (x2 - sm[t]) * si[t]; val2 = val2 * sg[t] + sb[t];
        float val3 = (x3 - sm[t]) * si[t]; val3 = val3 * sg[t] + sb[t];
        v0 = v0 + (val0 - v0) * 0.5f;
        v1 = v1 + (val1 - v1) * 0.5f;
        v2 = v2 + (val2 - v2) * 0.5f;
        v3 = v3 + (val3 - v3) * 0.5f;
        bool f0 = (v0 >= thr), f1 = (v1 >= thr), f2 = (v2 >= thr), f3 = (v3 >= thr);
        float4 o = {f0 ? 1.0f : 0.0f, f1 ? 1.0f : 0.0f, f2 ? 1.0f : 0.0f, f3 ? 1.0f : 0.0f};
        *(float4*)(out + ob + ((size_t)t << 22)) = o;
        if (f0) v0 = 0.f;
        if (f1) v1 = 0.f;
        if (f2) v2 = 0.f;
        if (f3) v3 = 0.f;
    }
}

// ---------------- launch ---------------------------------------------------
extern "C" void kernel_launch(void* const* d_in, const int* in_sizes, int n_in,
                              void* d_out, int out_size) {
    const float* x    = (const float*)d_in[0];  // inputs (B,L,D)
    const float* Wm   = (const float*)d_in[1];  // W (D*T, D)
    const float* bias = (const float*)d_in[2];  // b (D*T)
    const float* lng  = (const float*)d_in[3];
    const float* lnb  = (const float*)d_in[4];
    const float* bng  = (const float*)d_in[5];
    const float* bnb  = (const float*)d_in[6];
    const float* th   = (const float*)d_in[7];
    float* out = (float*)d_out;

    cudaFuncSetAttribute(gemm_kernel, cudaFuncAttributeMaxDynamicSharedMemorySize, GEMM_SMEM);

    ln_kernel<<<M_ROWS, 128>>>(x, lng, lnb);
    dim3 gg(N_COLS / 128, M_ROWS / 128);
    gemm_kernel<<<gg, 256, GEMM_SMEM>>>(Wm, bias);
    stats_kernel<<<M_ROWS, 256>>>();
    reduce_kernel<<<32, 256>>>();
    finalize_kernel<<<1, 16>>>();
    lif_kernel<<<(M_ROWS * K_DIM / 4) / 256, 256>>>(bng, bnb, th, out);
}